// round 7
// baseline (speedup 1.0000x reference)
#include <cuda_runtime.h>
#include <cuda_fp16.h>
#include <math.h>

#define NN 50000
#define EE 1600000
#define ETOT (EE + NN)          // edges + self loops
#define NBLK 196                // ceil(NN/256)

// ---------------- half2 <-> uint bit casts ----------------
__device__ __forceinline__ unsigned h2_to_u32(__half2 h) {
    return *reinterpret_cast<unsigned*>(&h);
}
__device__ __forceinline__ float2 u32_to_f2(unsigned u) {
    __half2 h = *reinterpret_cast<__half2*>(&u);
    return __half22float2(h);
}
__device__ __forceinline__ unsigned f2tf32(float f) {
    unsigned r;
    asm("cvt.rna.tf32.f32 %0, %1;" : "=r"(r) : "f"(f));
    return r;
}

// ---------------- scratch ----------------
__device__ __half  g_h1h[(size_t)NN * 128];   // layer1 linear out (fp16, for agg)
__device__ float   g_x2[(size_t)NN * 128];    // layer1 GAT out (relu), gemm2 input
__device__ __half  g_h2h[(size_t)NN * 64];    // layer2 linear out (fp16, for agg)
__device__ float   g_as1[NN * 2];
__device__ float   g_ad1[NN * 2];
__device__ float   g_as2[NN];
__device__ float   g_ad2[NN];
__device__ int     g_deg[NN];
__device__ int     g_rowptr[NN + 1];
__device__ int     g_cursor[NN];
__device__ int     g_csrc[ETOT];
__device__ int     g_bsum[256];
__device__ int     g_is64;

// ---------------- init: edge dtype probe + zero degrees ----------------
__global__ void k_init(const int* __restrict__ ei32) {
    int i = blockIdx.x * 256 + threadIdx.x;
    if (i < NN) g_deg[i] = 0;
    if (blockIdx.x == 0 && threadIdx.x == 0) {
        int all0 = 1;
        #pragma unroll
        for (int j = 0; j < 32; j++)
            if (ei32[2 * j + 1] != 0) all0 = 0;
        g_is64 = all0;           // int64 values < 50000 => odd words zero
        g_rowptr[NN] = ETOT;
    }
}

__device__ __forceinline__ int edge_at(const void* ei, long long idx) {
    if (g_is64) return (int)((const long long*)ei)[idx];
    return ((const int*)ei)[idx];
}

// ---------------- CSR build ----------------
__global__ void k_count(const void* __restrict__ ei) {
    int idx = blockIdx.x * 256 + threadIdx.x;
    if (idx >= ETOT) return;
    int d = (idx < EE) ? edge_at(ei, (long long)EE + idx) : (idx - EE);
    atomicAdd(&g_deg[d], 1);
}

__global__ void k_scanB() {   // chunk sums + exclusive scan of chunk sums
    __shared__ __align__(16) int sm[256];
    int t = threadIdx.x;
    int sum = 0;
    if (t < NBLK) {
        int base = t * 256;
        if (base + 256 <= NN) {
            const int4* p = (const int4*)&g_deg[base];
            #pragma unroll 8
            for (int j = 0; j < 64; j++) {
                int4 v = p[j];
                sum += v.x + v.y + v.z + v.w;
            }
        } else {
            for (int j = base; j < NN; j++) sum += g_deg[j];
        }
    }
    sm[t] = sum; __syncthreads();
    for (int off = 1; off < 256; off <<= 1) {
        int x = (t >= off) ? sm[t - off] : 0;
        __syncthreads();
        sm[t] += x;
        __syncthreads();
    }
    if (t < NBLK) g_bsum[t] = sm[t] - sum;   // exclusive
}

__global__ void k_scanC() {
    __shared__ __align__(16) int sm[256];
    int b = blockIdx.x, t = threadIdx.x;
    int i = b * 256 + t;
    int v = (i < NN) ? g_deg[i] : 0;
    sm[t] = v; __syncthreads();
    for (int off = 1; off < 256; off <<= 1) {
        int x = (t >= off) ? sm[t - off] : 0;
        __syncthreads();
        sm[t] += x;
        __syncthreads();
    }
    if (i < NN) {
        int rp = g_bsum[b] + sm[t] - v;
        g_rowptr[i] = rp;
        g_cursor[i] = rp;
    }
}

__global__ void k_scatter(const void* __restrict__ ei) {
    int idx = blockIdx.x * 256 + threadIdx.x;
    if (idx >= ETOT) return;
    int s, d;
    if (idx < EE) {
        s = edge_at(ei, idx);
        d = edge_at(ei, (long long)EE + idx);
    } else {
        s = d = idx - EE;
    }
    int pos = atomicAdd(&g_cursor[d], 1);
    g_csrc[pos] = s;
}

// ---------------- TF32 tensor-core GEMM + fused attention-score epilogue --------
// D[M,NOUT] = X[M,K] @ W[K,NOUT]; mma.m16n8k8 tf32.
// Block: 256 thr (8 warps), tile M=128 (16 rows/warp), full NOUT, K chunk = 32.
// Fragments staged frag-packed in smem at STS time.
template<int K, int NOUT, int H>
__global__ void __launch_bounds__(256, 2) k_gemm_tc(
        const float* __restrict__ X, const float* __restrict__ W,
        const float* __restrict__ att_s, const float* __restrict__ att_d,
        __half* __restrict__ Hout16, float* __restrict__ as_, float* __restrict__ ad_,
        int n) {
    constexpr int NT = NOUT / 8;    // n-tiles (16 for 128, 8 for 64)
    constexpr int MT = 128;         // rows per block
    constexpr int KT = 32;          // k chunk (4 k8-steps)

    __shared__ unsigned af[4 * 8 * 32 * 4];        // A frags: [k8][warp][lane][4]
    __shared__ unsigned wsf[4 * NT * 32 * 2];      // B frags: [k8][ntile][lane][2]

    int tid = threadIdx.x;
    int w = tid >> 5, l = tid & 31;
    int tg = l & 3;      // tid_in_group
    int gp = l >> 2;     // groupID
    int m0 = blockIdx.x * MT;

    float acc[NT][4];
#pragma unroll
    for (int nt = 0; nt < NT; nt++)
#pragma unroll
        for (int c = 0; c < 4; c++) acc[nt][c] = 0.f;

    for (int k0 = 0; k0 < K; k0 += KT) {
        // ---- stage A: X[m0..m0+127][k0..k0+31] -> frag-packed tf32 ----
#pragma unroll
        for (int i = tid; i < MT * KT / 4; i += 256) {
            int r  = i >> 3;          // row in tile (KT/4 = 8 float4 per row)
            int c4 = i & 7;
            int gr = m0 + r;
            float4 v = make_float4(0.f, 0.f, 0.f, 0.f);
            if (gr < n) v = *(const float4*)&X[(size_t)gr * K + k0 + c4 * 4];
            float vj[4] = {v.x, v.y, v.z, v.w};
#pragma unroll
            for (int j = 0; j < 4; j++) {
                int kk   = c4 * 4 + j;                 // 0..31
                int k8   = kk >> 3, kin = kk & 7;
                int lane = (r & 7) * 4 + (kin & 3);
                int reg  = ((r >> 3) & 1) + 2 * (kin >> 2);
                af[(((k8 << 3) + (r >> 4)) * 32 + lane) * 4 + reg] = f2tf32(vj[j]);
            }
        }
        // ---- stage B: W[k0..k0+31][0..NOUT-1] -> frag-packed tf32 ----
#pragma unroll
        for (int i = tid; i < KT * NOUT / 4; i += 256) {
            int r  = i / (NOUT / 4);                   // k in chunk
            int c4 = i % (NOUT / 4);
            float4 v = *(const float4*)&W[(size_t)(k0 + r) * NOUT + c4 * 4];
            float vj[4] = {v.x, v.y, v.z, v.w};
#pragma unroll
            for (int j = 0; j < 4; j++) {
                int nn   = c4 * 4 + j;
                int nt   = nn >> 3, nin = nn & 7;
                int lane = nin * 4 + (r & 3);
                int reg  = (r >> 2) & 1;
                int k8   = r >> 3;
                wsf[((k8 * NT + nt) * 32 + lane) * 2 + reg] = f2tf32(vj[j]);
            }
        }
        __syncthreads();
        // ---- compute ----
#pragma unroll
        for (int k8 = 0; k8 < 4; k8++) {
            uint4 A = *(const uint4*)&af[(((k8 << 3) + w) * 32 + l) * 4];
#pragma unroll
            for (int nt = 0; nt < NT; nt++) {
                uint2 B = *(const uint2*)&wsf[((k8 * NT + nt) * 32 + l) * 2];
                asm volatile(
                    "mma.sync.aligned.m16n8k8.row.col.f32.tf32.tf32.f32 "
                    "{%0,%1,%2,%3},{%4,%5,%6,%7},{%8,%9},{%0,%1,%2,%3};"
                    : "+f"(acc[nt][0]), "+f"(acc[nt][1]),
                      "+f"(acc[nt][2]), "+f"(acc[nt][3])
                    : "r"(A.x), "r"(A.y), "r"(A.z), "r"(A.w),
                      "r"(B.x), "r"(B.y));
            }
        }
        __syncthreads();
    }

    // ---- epilogue: fp16 h store + attention scores ----
    // C frag: c0=(gp, tg*2), c1=(gp, tg*2+1), c2=(gp+8, tg*2), c3=(gp+8, tg*2+1)
    int r0 = m0 + w * 16 + gp;
    int r1 = r0 + 8;

    float ps0[H], pd0[H], ps1[H], pd1[H];
#pragma unroll
    for (int h = 0; h < H; h++) { ps0[h] = pd0[h] = ps1[h] = pd1[h] = 0.f; }

#pragma unroll
    for (int nt = 0; nt < NT; nt++) {
        int col = nt * 8 + tg * 2;
        float s0 = att_s[col], s1 = att_s[col + 1];
        float d0 = att_d[col], d1 = att_d[col + 1];
        int h = (H == 2) ? (nt / (NT / 2)) : 0;
        ps0[h] += acc[nt][0] * s0 + acc[nt][1] * s1;
        pd0[h] += acc[nt][0] * d0 + acc[nt][1] * d1;
        ps1[h] += acc[nt][2] * s0 + acc[nt][3] * s1;
        pd1[h] += acc[nt][2] * d0 + acc[nt][3] * d1;
    }
    // reduce over the 4 lanes of each group (they own disjoint cols of the row)
#pragma unroll
    for (int h = 0; h < H; h++) {
#pragma unroll
        for (int o = 1; o < 4; o <<= 1) {
            ps0[h] += __shfl_xor_sync(0xffffffffu, ps0[h], o);
            pd0[h] += __shfl_xor_sync(0xffffffffu, pd0[h], o);
            ps1[h] += __shfl_xor_sync(0xffffffffu, ps1[h], o);
            pd1[h] += __shfl_xor_sync(0xffffffffu, pd1[h], o);
        }
    }

    if (r0 < n) {
#pragma unroll
        for (int nt = 0; nt < NT; nt++) {
            int col = nt * 8 + tg * 2;
            *(unsigned*)&Hout16[(size_t)r0 * NOUT + col] =
                h2_to_u32(__floats2half2_rn(acc[nt][0], acc[nt][1]));
        }
        if (tg == 0) {
#pragma unroll
            for (int h = 0; h < H; h++) {
                as_[r0 * H + h] = ps0[h];
                ad_[r0 * H + h] = pd0[h];
            }
        }
    }
    if (r1 < n) {
#pragma unroll
        for (int nt = 0; nt < NT; nt++) {
            int col = nt * 8 + tg * 2;
            *(unsigned*)&Hout16[(size_t)r1 * NOUT + col] =
                h2_to_u32(__floats2half2_rn(acc[nt][2], acc[nt][3]));
        }
        if (tg == 0) {
#pragma unroll
            for (int h = 0; h < H; h++) {
                as_[r1 * H + h] = ps1[h];
                ad_[r1 * H + h] = pd1[h];
            }
        }
    }
}

// ---------------- single-pass softmax aggregation (warp per dst node) ----------------
template<int NOUT, int H, int VEC, bool RELU, bool LOGSM>
__global__ void k_agg(const __half* __restrict__ Hsrc,
                      const float* __restrict__ as_, const float* __restrict__ ad_,
                      const float* __restrict__ bias, float* __restrict__ out, int n) {
    int node = blockIdx.x * (blockDim.x / 32) + (threadIdx.x >> 5);
    int lane = threadIdx.x & 31;
    if (node >= n) return;

    int head = (lane * VEC) / 64;
    float adv = ad_[node * H + head];
    int beg = g_rowptr[node];
    int end = g_rowptr[node + 1];

    float den = 0.f;
    float acc[VEC];
#pragma unroll
    for (int j = 0; j < VEC; j++) acc[j] = 0.f;

    const __half* Hbase = Hsrc + lane * VEC;

    int i = beg;
    for (; i + 4 <= end; i += 4) {
        int s0 = g_csrc[i],     s1 = g_csrc[i + 1];
        int s2 = g_csrc[i + 2], s3 = g_csrc[i + 3];
        float v0 = as_[s0 * H + head] + adv;
        float v1 = as_[s1 * H + head] + adv;
        float v2 = as_[s2 * H + head] + adv;
        float v3 = as_[s3 * H + head] + adv;
        v0 = v0 > 0.f ? v0 : 0.2f * v0;
        v1 = v1 > 0.f ? v1 : 0.2f * v1;
        v2 = v2 > 0.f ? v2 : 0.2f * v2;
        v3 = v3 > 0.f ? v3 : 0.2f * v3;
        float w0 = __expf(v0), w1 = __expf(v1);
        float w2 = __expf(v2), w3 = __expf(v3);
        den += (w0 + w1) + (w2 + w3);
        if (VEC == 4) {
            uint2 u0 = *(const uint2*)(Hbase + (size_t)s0 * NOUT);
            uint2 u1 = *(const uint2*)(Hbase + (size_t)s1 * NOUT);
            uint2 u2 = *(const uint2*)(Hbase + (size_t)s2 * NOUT);
            uint2 u3 = *(const uint2*)(Hbase + (size_t)s3 * NOUT);
            float2 a0 = u32_to_f2(u0.x), a1 = u32_to_f2(u0.y);
            float2 b0 = u32_to_f2(u1.x), b1 = u32_to_f2(u1.y);
            float2 c0 = u32_to_f2(u2.x), c1 = u32_to_f2(u2.y);
            float2 d0 = u32_to_f2(u3.x), d1 = u32_to_f2(u3.y);
            acc[0] += (w0 * a0.x + w1 * b0.x) + (w2 * c0.x + w3 * d0.x);
            acc[1] += (w0 * a0.y + w1 * b0.y) + (w2 * c0.y + w3 * d0.y);
            acc[2] += (w0 * a1.x + w1 * b1.x) + (w2 * c1.x + w3 * d1.x);
            acc[3] += (w0 * a1.y + w1 * b1.y) + (w2 * c1.y + w3 * d1.y);
        } else {
            unsigned u0 = *(const unsigned*)(Hbase + (size_t)s0 * NOUT);
            unsigned u1 = *(const unsigned*)(Hbase + (size_t)s1 * NOUT);
            unsigned u2 = *(const unsigned*)(Hbase + (size_t)s2 * NOUT);
            unsigned u3 = *(const unsigned*)(Hbase + (size_t)s3 * NOUT);
            float2 a = u32_to_f2(u0), b = u32_to_f2(u1);
            float2 c = u32_to_f2(u2), d = u32_to_f2(u3);
            acc[0] += (w0 * a.x + w1 * b.x) + (w2 * c.x + w3 * d.x);
            acc[1] += (w0 * a.y + w1 * b.y) + (w2 * c.y + w3 * d.y);
        }
    }
    for (; i < end; i++) {
        int s = g_csrc[i];
        float v = as_[s * H + head] + adv;
        v = v > 0.f ? v : 0.2f * v;
        float w = __expf(v);
        den += w;
        if (VEC == 4) {
            uint2 u = *(const uint2*)(Hbase + (size_t)s * NOUT);
            float2 a0 = u32_to_f2(u.x);
            float2 a1 = u32_to_f2(u.y);
            acc[0] += w * a0.x; acc[1] += w * a0.y;
            acc[2] += w * a1.x; acc[3] += w * a1.y;
        } else {
            unsigned u = *(const unsigned*)(Hbase + (size_t)s * NOUT);
            float2 a = u32_to_f2(u);
            acc[0] += w * a.x; acc[1] += w * a.y;
        }
    }

    float inv = 1.f / (den + 1e-16f);
    float o[VEC];
#pragma unroll
    for (int j = 0; j < VEC; j++) {
        o[j] = acc[j] * inv + bias[lane * VEC + j];
        if (RELU) o[j] = fmaxf(o[j], 0.f);
    }

    if (LOGSM) {   // VEC==2, NOUT==64: warp holds all 64 outputs
        float m = fmaxf(o[0], o[1]);
#pragma unroll
        for (int off = 16; off > 0; off >>= 1)
            m = fmaxf(m, __shfl_xor_sync(0xffffffffu, m, off));
        float s_ = __expf(o[0] - m) + __expf(o[1] - m);
#pragma unroll
        for (int off = 16; off > 0; off >>= 1)
            s_ += __shfl_xor_sync(0xffffffffu, s_, off);
        float ls = m + logf(s_);
#pragma unroll
        for (int j = 0; j < VEC; j++) o[j] -= ls;
    }

    float* op = out + (size_t)node * NOUT + lane * VEC;
    if (VEC == 4) *(float4*)op = make_float4(o[0], o[1], o[2], o[3]);
    else          *(float2*)op = make_float2(o[0], o[1]);
}

// ---------------- launch ----------------
extern "C" void kernel_launch(void* const* d_in, const int* in_sizes, int n_in,
                              void* d_out, int out_size) {
    const float* x    = (const float*)d_in[0];
    const void*  ei   = d_in[1];
    const float* W1   = (const float*)d_in[2];
    const float* asw1 = (const float*)d_in[3];
    const float* adw1 = (const float*)d_in[4];
    const float* b1   = (const float*)d_in[5];
    const float* W2   = (const float*)d_in[6];
    const float* asw2 = (const float*)d_in[7];
    const float* adw2 = (const float*)d_in[8];
    const float* b2   = (const float*)d_in[9];
    float*       out  = (float*)d_out;

    const int EB = (ETOT + 255) / 256;
    const int WB = (NN + 7) / 8;
    const int GB = (NN + 127) / 128;    // gemm grid (128 rows/block)

    __half* h1h = nullptr; cudaGetSymbolAddress((void**)&h1h, g_h1h);
    __half* h2h = nullptr; cudaGetSymbolAddress((void**)&h2h, g_h2h);
    float*  x2  = nullptr; cudaGetSymbolAddress((void**)&x2,  g_x2);
    float*  as1 = nullptr; cudaGetSymbolAddress((void**)&as1, g_as1);
    float*  ad1 = nullptr; cudaGetSymbolAddress((void**)&ad1, g_ad1);
    float*  as2 = nullptr; cudaGetSymbolAddress((void**)&as2, g_as2);
    float*  ad2 = nullptr; cudaGetSymbolAddress((void**)&ad2, g_ad2);

    // index 3 = gemm1 (ncu capture lands there)
    k_init<<<NBLK, 256>>>((const int*)ei);                                   // 0
    k_count<<<EB, 256>>>(ei);                                                // 1
    k_scanB<<<1, 256>>>();                                                   // 2
    k_gemm_tc<256, 128, 2><<<GB, 256>>>(                                     // 3
        x, W1, asw1, adw1, h1h, as1, ad1, NN);
    k_scanC<<<NBLK, 256>>>();                                                // 4
    k_scatter<<<EB, 256>>>(ei);                                              // 5
    k_agg<128, 2, 4, true, false><<<WB, 256>>>(h1h, as1, ad1, b1, x2, NN);   // 6
    k_gemm_tc<128, 64, 1><<<GB, 256>>>(                                      // 7
        x2, W2, asw2, adw2, h2h, as2, ad2, NN);
    k_agg<64, 1, 2, false, true><<<WB, 256>>>(h2h, as2, ad2, b2, out, NN);   // 8
}

// round 8
// speedup vs baseline: 1.2762x; 1.2762x over previous
#include <cuda_runtime.h>
#include <cuda_fp16.h>
#include <math.h>

#define NN 50000
#define EE 1600000
#define ETOT (EE + NN)          // edges + self loops
#define NBLK 196                // ceil(NN/256)

// ---------------- bit casts / conversions ----------------
__device__ __forceinline__ unsigned h2_to_u32(__half2 h) {
    return *reinterpret_cast<unsigned*>(&h);
}
__device__ __forceinline__ float2 u32_to_f2(unsigned u) {
    __half2 h = *reinterpret_cast<__half2*>(&u);
    return __half22float2(h);
}
__device__ __forceinline__ unsigned f2tf32(float f) {
    unsigned r;
    asm("cvt.rna.tf32.f32 %0, %1;" : "=r"(r) : "f"(f));
    return r;
}

// ---------------- scratch ----------------
__device__ __half    g_h1h[(size_t)NN * 128];   // layer1 linear out (fp16, for agg)
__device__ float     g_x2[(size_t)NN * 128];    // layer1 GAT out (relu), gemm2 input
__device__ __half    g_h2h[(size_t)NN * 64];    // layer2 linear out (fp16, for agg)
__device__ float     g_as1[NN * 2];
__device__ float     g_ad1[NN * 2];
__device__ float     g_as2[NN];
__device__ float     g_ad2[NN];
__device__ int       g_deg[NN];
__device__ int       g_rowptr[NN + 1];
__device__ int       g_cursor[NN];
__device__ int       g_csrc[ETOT];
__device__ int       g_bsum[256];
__device__ int       g_is64;
__device__ unsigned  g_wf1[256 * 128];          // W1 fragment-packed tf32
__device__ unsigned  g_wf2[128 * 64];           // W2 fragment-packed tf32

// ---------------- init: edge dtype probe + zero degrees ----------------
__global__ void k_init(const int* __restrict__ ei32) {
    int i = blockIdx.x * 256 + threadIdx.x;
    if (i < NN) g_deg[i] = 0;
    if (blockIdx.x == 0 && threadIdx.x == 0) {
        int all0 = 1;
        #pragma unroll
        for (int j = 0; j < 32; j++)
            if (ei32[2 * j + 1] != 0) all0 = 0;
        g_is64 = all0;           // int64 values < 50000 => odd words zero
        g_rowptr[NN] = ETOT;
    }
}

__device__ __forceinline__ int edge_at(const void* ei, long long idx) {
    if (g_is64) return (int)((const long long*)ei)[idx];
    return ((const int*)ei)[idx];
}

// ---------------- CSR build ----------------
__global__ void k_count(const void* __restrict__ ei) {
    int idx = blockIdx.x * 256 + threadIdx.x;
    if (idx >= ETOT) return;
    int d = (idx < EE) ? edge_at(ei, (long long)EE + idx) : (idx - EE);
    atomicAdd(&g_deg[d], 1);
}

__global__ void k_scanB() {   // chunk sums + exclusive scan of chunk sums
    __shared__ __align__(16) int sm[256];
    int t = threadIdx.x;
    int sum = 0;
    if (t < NBLK) {
        int base = t * 256;
        if (base + 256 <= NN) {
            const int4* p = (const int4*)&g_deg[base];
            #pragma unroll 8
            for (int j = 0; j < 64; j++) {
                int4 v = p[j];
                sum += v.x + v.y + v.z + v.w;
            }
        } else {
            for (int j = base; j < NN; j++) sum += g_deg[j];
        }
    }
    sm[t] = sum; __syncthreads();
    for (int off = 1; off < 256; off <<= 1) {
        int x = (t >= off) ? sm[t - off] : 0;
        __syncthreads();
        sm[t] += x;
        __syncthreads();
    }
    if (t < NBLK) g_bsum[t] = sm[t] - sum;   // exclusive
}

__global__ void k_scanC() {
    __shared__ __align__(16) int sm[256];
    int b = blockIdx.x, t = threadIdx.x;
    int i = b * 256 + t;
    int v = (i < NN) ? g_deg[i] : 0;
    sm[t] = v; __syncthreads();
    for (int off = 1; off < 256; off <<= 1) {
        int x = (t >= off) ? sm[t - off] : 0;
        __syncthreads();
        sm[t] += x;
        __syncthreads();
    }
    if (i < NN) {
        int rp = g_bsum[b] + sm[t] - v;
        g_rowptr[i] = rp;
        g_cursor[i] = rp;
    }
}

__global__ void k_scatter(const void* __restrict__ ei) {
    int idx = blockIdx.x * 256 + threadIdx.x;
    if (idx >= ETOT) return;
    int s, d;
    if (idx < EE) {
        s = edge_at(ei, idx);
        d = edge_at(ei, (long long)EE + idx);
    } else {
        s = d = idx - EE;
    }
    int pos = atomicAdd(&g_cursor[d], 1);
    g_csrc[pos] = s;
}

// ---------------- W fragment pre-pack (runs once, tiny) ----------------
// B-frag mapping (m16n8k8.row.col, verified R7): for W[k][n]:
//   k8 = k>>3, nt = n>>3, lane = (n&7)*4 + (k&3), reg = (k>>2)&1
template<int K, int NOUT>
__global__ void k_packW(const float* __restrict__ W, unsigned* __restrict__ wf) {
    int i = blockIdx.x * 256 + threadIdx.x;
    if (i >= K * NOUT) return;
    int k = i / NOUT, n = i % NOUT;
    constexpr int NT = NOUT / 8;
    int k8 = k >> 3, nt = n >> 3;
    int lane = (n & 7) * 4 + (k & 3);
    int reg = (k >> 2) & 1;
    wf[(((k8 * NT + nt) * 32) + lane) * 2 + reg] = f2tf32(W[i]);
}

// ---------------- TF32 tensor-core GEMM + fused attention-score epilogue --------
// A natural-layout in smem (tf32), fragments via conflict-free LDS.32;
// B fragments straight from pre-packed global via coalesced LDG.64.
template<int K, int NOUT, int H>
__global__ void __launch_bounds__(256, 2) k_gemm_tc(
        const float* __restrict__ X, const unsigned* __restrict__ wf,
        const float* __restrict__ att_s, const float* __restrict__ att_d,
        __half* __restrict__ Hout16, float* __restrict__ as_, float* __restrict__ ad_,
        int n) {
    constexpr int NT = NOUT / 8;    // n-tiles (16 for 128, 8 for 64)
    constexpr int MT = 128;         // rows per block
    constexpr int KT = 32;          // k chunk (4 k8-steps)
    constexpr int XS = KT + 4;      // padded word stride (36)

    __shared__ __align__(16) unsigned xs[MT][XS];

    int tid = threadIdx.x;
    int w = tid >> 5, l = tid & 31;
    int tg = l & 3;      // tid in quad
    int gp = l >> 2;     // quad id
    int m0 = blockIdx.x * MT;
    int rowA = w * 16 + gp;

    float acc[NT][4];
#pragma unroll
    for (int nt = 0; nt < NT; nt++)
#pragma unroll
        for (int c = 0; c < 4; c++) acc[nt][c] = 0.f;

    for (int k0 = 0; k0 < K; k0 += KT) {
        // ---- stage A tile (row-major, tf32-converted, uint4 stores) ----
#pragma unroll
        for (int i = tid; i < MT * KT / 4; i += 256) {
            int r  = i >> 3;          // KT/4 = 8 float4 per row
            int c4 = i & 7;
            int gr = m0 + r;
            float4 v = make_float4(0.f, 0.f, 0.f, 0.f);
            if (gr < n) v = *(const float4*)&X[(size_t)gr * K + k0 + c4 * 4];
            uint4 u;
            u.x = f2tf32(v.x); u.y = f2tf32(v.y);
            u.z = f2tf32(v.z); u.w = f2tf32(v.w);
            *(uint4*)&xs[r][c4 * 4] = u;
        }
        __syncthreads();
        int kb = k0 >> 3;   // global k8 base
#pragma unroll
        for (int k8 = 0; k8 < 4; k8++) {
            unsigned a0 = xs[rowA][k8 * 8 + tg];
            unsigned a1 = xs[rowA + 8][k8 * 8 + tg];
            unsigned a2 = xs[rowA][k8 * 8 + tg + 4];
            unsigned a3 = xs[rowA + 8][k8 * 8 + tg + 4];
            const uint2* wp = (const uint2*)wf + (size_t)(kb + k8) * NT * 32 + l;
#pragma unroll
            for (int nt = 0; nt < NT; nt++) {
                uint2 B = wp[nt * 32];
                asm volatile(
                    "mma.sync.aligned.m16n8k8.row.col.f32.tf32.tf32.f32 "
                    "{%0,%1,%2,%3},{%4,%5,%6,%7},{%8,%9},{%0,%1,%2,%3};"
                    : "+f"(acc[nt][0]), "+f"(acc[nt][1]),
                      "+f"(acc[nt][2]), "+f"(acc[nt][3])
                    : "r"(a0), "r"(a1), "r"(a2), "r"(a3),
                      "r"(B.x), "r"(B.y));
            }
        }
        __syncthreads();
    }

    // ---- epilogue: fp16 h store + attention scores (verified R7) ----
    // C frag: c0=(gp, tg*2), c1=(gp, tg*2+1), c2=(gp+8, tg*2), c3=(gp+8, tg*2+1)
    int r0 = m0 + w * 16 + gp;
    int r1 = r0 + 8;

    float ps0[H], pd0[H], ps1[H], pd1[H];
#pragma unroll
    for (int h = 0; h < H; h++) { ps0[h] = pd0[h] = ps1[h] = pd1[h] = 0.f; }

#pragma unroll
    for (int nt = 0; nt < NT; nt++) {
        int col = nt * 8 + tg * 2;
        float s0 = att_s[col], s1 = att_s[col + 1];
        float d0 = att_d[col], d1 = att_d[col + 1];
        int h = (H == 2) ? (nt / (NT / 2)) : 0;
        ps0[h] += acc[nt][0] * s0 + acc[nt][1] * s1;
        pd0[h] += acc[nt][0] * d0 + acc[nt][1] * d1;
        ps1[h] += acc[nt][2] * s0 + acc[nt][3] * s1;
        pd1[h] += acc[nt][2] * d0 + acc[nt][3] * d1;
    }
#pragma unroll
    for (int h = 0; h < H; h++) {
#pragma unroll
        for (int o = 1; o < 4; o <<= 1) {
            ps0[h] += __shfl_xor_sync(0xffffffffu, ps0[h], o);
            pd0[h] += __shfl_xor_sync(0xffffffffu, pd0[h], o);
            ps1[h] += __shfl_xor_sync(0xffffffffu, ps1[h], o);
            pd1[h] += __shfl_xor_sync(0xffffffffu, pd1[h], o);
        }
    }

    if (r0 < n) {
#pragma unroll
        for (int nt = 0; nt < NT; nt++) {
            int col = nt * 8 + tg * 2;
            *(unsigned*)&Hout16[(size_t)r0 * NOUT + col] =
                h2_to_u32(__floats2half2_rn(acc[nt][0], acc[nt][1]));
        }
        if (tg == 0) {
#pragma unroll
            for (int h = 0; h < H; h++) {
                as_[r0 * H + h] = ps0[h];
                ad_[r0 * H + h] = pd0[h];
            }
        }
    }
    if (r1 < n) {
#pragma unroll
        for (int nt = 0; nt < NT; nt++) {
            int col = nt * 8 + tg * 2;
            *(unsigned*)&Hout16[(size_t)r1 * NOUT + col] =
                h2_to_u32(__floats2half2_rn(acc[nt][2], acc[nt][3]));
        }
        if (tg == 0) {
#pragma unroll
            for (int h = 0; h < H; h++) {
                as_[r1 * H + h] = ps1[h];
                ad_[r1 * H + h] = pd1[h];
            }
        }
    }
}

// ---------------- single-pass softmax aggregation (warp per dst node) ----------------
template<int NOUT, int H, int VEC, bool RELU, bool LOGSM>
__global__ void k_agg(const __half* __restrict__ Hsrc,
                      const float* __restrict__ as_, const float* __restrict__ ad_,
                      const float* __restrict__ bias, float* __restrict__ out, int n) {
    int node = blockIdx.x * (blockDim.x / 32) + (threadIdx.x >> 5);
    int lane = threadIdx.x & 31;
    if (node >= n) return;

    int head = (lane * VEC) / 64;
    float adv = ad_[node * H + head];
    int beg = g_rowptr[node];
    int end = g_rowptr[node + 1];

    float den = 0.f;
    float acc[VEC];
#pragma unroll
    for (int j = 0; j < VEC; j++) acc[j] = 0.f;

    const __half* Hbase = Hsrc + lane * VEC;

    int i = beg;
    for (; i + 4 <= end; i += 4) {
        int s0 = g_csrc[i],     s1 = g_csrc[i + 1];
        int s2 = g_csrc[i + 2], s3 = g_csrc[i + 3];
        float v0 = as_[s0 * H + head] + adv;
        float v1 = as_[s1 * H + head] + adv;
        float v2 = as_[s2 * H + head] + adv;
        float v3 = as_[s3 * H + head] + adv;
        v0 = v0 > 0.f ? v0 : 0.2f * v0;
        v1 = v1 > 0.f ? v1 : 0.2f * v1;
        v2 = v2 > 0.f ? v2 : 0.2f * v2;
        v3 = v3 > 0.f ? v3 : 0.2f * v3;
        float w0 = __expf(v0), w1 = __expf(v1);
        float w2 = __expf(v2), w3 = __expf(v3);
        den += (w0 + w1) + (w2 + w3);
        if (VEC == 4) {
            uint2 u0 = *(const uint2*)(Hbase + (size_t)s0 * NOUT);
            uint2 u1 = *(const uint2*)(Hbase + (size_t)s1 * NOUT);
            uint2 u2 = *(const uint2*)(Hbase + (size_t)s2 * NOUT);
            uint2 u3 = *(const uint2*)(Hbase + (size_t)s3 * NOUT);
            float2 a0 = u32_to_f2(u0.x), a1 = u32_to_f2(u0.y);
            float2 b0 = u32_to_f2(u1.x), b1 = u32_to_f2(u1.y);
            float2 c0 = u32_to_f2(u2.x), c1 = u32_to_f2(u2.y);
            float2 d0 = u32_to_f2(u3.x), d1 = u32_to_f2(u3.y);
            acc[0] += (w0 * a0.x + w1 * b0.x) + (w2 * c0.x + w3 * d0.x);
            acc[1] += (w0 * a0.y + w1 * b0.y) + (w2 * c0.y + w3 * d0.y);
            acc[2] += (w0 * a1.x + w1 * b1.x) + (w2 * c1.x + w3 * d1.x);
            acc[3] += (w0 * a1.y + w1 * b1.y) + (w2 * c1.y + w3 * d1.y);
        } else {
            unsigned u0 = *(const unsigned*)(Hbase + (size_t)s0 * NOUT);
            unsigned u1 = *(const unsigned*)(Hbase + (size_t)s1 * NOUT);
            unsigned u2 = *(const unsigned*)(Hbase + (size_t)s2 * NOUT);
            unsigned u3 = *(const unsigned*)(Hbase + (size_t)s3 * NOUT);
            float2 a = u32_to_f2(u0), b = u32_to_f2(u1);
            float2 c = u32_to_f2(u2), d = u32_to_f2(u3);
            acc[0] += (w0 * a.x + w1 * b.x) + (w2 * c.x + w3 * d.x);
            acc[1] += (w0 * a.y + w1 * b.y) + (w2 * c.y + w3 * d.y);
        }
    }
    for (; i < end; i++) {
        int s = g_csrc[i];
        float v = as_[s * H + head] + adv;
        v = v > 0.f ? v : 0.2f * v;
        float w = __expf(v);
        den += w;
        if (VEC == 4) {
            uint2 u = *(const uint2*)(Hbase + (size_t)s * NOUT);
            float2 a0 = u32_to_f2(u.x);
            float2 a1 = u32_to_f2(u.y);
            acc[0] += w * a0.x; acc[1] += w * a0.y;
            acc[2] += w * a1.x; acc[3] += w * a1.y;
        } else {
            unsigned u = *(const unsigned*)(Hbase + (size_t)s * NOUT);
            float2 a = u32_to_f2(u);
            acc[0] += w * a.x; acc[1] += w * a.y;
        }
    }

    float inv = 1.f / (den + 1e-16f);
    float o[VEC];
#pragma unroll
    for (int j = 0; j < VEC; j++) {
        o[j] = acc[j] * inv + bias[lane * VEC + j];
        if (RELU) o[j] = fmaxf(o[j], 0.f);
    }

    if (LOGSM) {   // VEC==2, NOUT==64: warp holds all 64 outputs
        float m = fmaxf(o[0], o[1]);
#pragma unroll
        for (int off = 16; off > 0; off >>= 1)
            m = fmaxf(m, __shfl_xor_sync(0xffffffffu, m, off));
        float s_ = __expf(o[0] - m) + __expf(o[1] - m);
#pragma unroll
        for (int off = 16; off > 0; off >>= 1)
            s_ += __shfl_xor_sync(0xffffffffu, s_, off);
        float ls = m + logf(s_);
#pragma unroll
        for (int j = 0; j < VEC; j++) o[j] -= ls;
    }

    float* op = out + (size_t)node * NOUT + lane * VEC;
    if (VEC == 4) *(float4*)op = make_float4(o[0], o[1], o[2], o[3]);
    else          *(float2*)op = make_float2(o[0], o[1]);
}

// ---------------- launch ----------------
extern "C" void kernel_launch(void* const* d_in, const int* in_sizes, int n_in,
                              void* d_out, int out_size) {
    const float* x    = (const float*)d_in[0];
    const void*  ei   = d_in[1];
    const float* W1   = (const float*)d_in[2];
    const float* asw1 = (const float*)d_in[3];
    const float* adw1 = (const float*)d_in[4];
    const float* b1   = (const float*)d_in[5];
    const float* W2   = (const float*)d_in[6];
    const float* asw2 = (const float*)d_in[7];
    const float* adw2 = (const float*)d_in[8];
    const float* b2   = (const float*)d_in[9];
    float*       out  = (float*)d_out;

    const int EB = (ETOT + 255) / 256;
    const int WB = (NN + 7) / 8;
    const int GB = (NN + 127) / 128;    // gemm grid (128 rows/block)

    __half*   h1h = nullptr; cudaGetSymbolAddress((void**)&h1h, g_h1h);
    __half*   h2h = nullptr; cudaGetSymbolAddress((void**)&h2h, g_h2h);
    float*    x2  = nullptr; cudaGetSymbolAddress((void**)&x2,  g_x2);
    float*    as1 = nullptr; cudaGetSymbolAddress((void**)&as1, g_as1);
    float*    ad1 = nullptr; cudaGetSymbolAddress((void**)&ad1, g_ad1);
    float*    as2 = nullptr; cudaGetSymbolAddress((void**)&as2, g_as2);
    float*    ad2 = nullptr; cudaGetSymbolAddress((void**)&ad2, g_ad2);
    unsigned* wf1 = nullptr; cudaGetSymbolAddress((void**)&wf1, g_wf1);
    unsigned* wf2 = nullptr; cudaGetSymbolAddress((void**)&wf2, g_wf2);

    // index 3 = gemm1 (ncu capture lands there)
    k_init<<<NBLK, 256>>>((const int*)ei);                                   // 0
    k_count<<<EB, 256>>>(ei);                                                // 1
    k_packW<256, 128><<<(256 * 128 + 255) / 256, 256>>>(W1, wf1);            // 2
    k_gemm_tc<256, 128, 2><<<GB, 256>>>(                                     // 3
        x, wf1, asw1, adw1, h1h, as1, ad1, NN);
    k_scanB<<<1, 256>>>();                                                   // 4
    k_scanC<<<NBLK, 256>>>();                                                // 5
    k_scatter<<<EB, 256>>>(ei);                                              // 6
    k_agg<128, 2, 4, true, false><<<WB, 256>>>(h1h, as1, ad1, b1, x2, NN);   // 7
    k_packW<128, 64><<<(128 * 64 + 255) / 256, 256>>>(W2, wf2);              // 8
    k_gemm_tc<128, 64, 1><<<GB, 256>>>(                                      // 9
        x2, wf2, asw2, adw2, h2h, as2, ad2, NN);
    k_agg<64, 1, 2, false, true><<<WB, 256>>>(h2h, as2, ad2, b2, out, NN);   // 10
}

// round 9
// speedup vs baseline: 1.4183x; 1.1114x over previous
#include <cuda_runtime.h>
#include <cuda_fp16.h>
#include <math.h>

#define NN 50000
#define EE 1600000
#define ETOT (EE + NN)          // edges + self loops
#define NBLK 196                // ceil(NN/256)

// ---------------- bit casts / conversions ----------------
__device__ __forceinline__ unsigned h2_to_u32(__half2 h) {
    return *reinterpret_cast<unsigned*>(&h);
}
__device__ __forceinline__ float2 u32_to_f2(unsigned u) {
    __half2 h = *reinterpret_cast<__half2*>(&u);
    return __half22float2(h);
}
__device__ __forceinline__ unsigned f2tf32(float f) {
    unsigned r;
    asm("cvt.rna.tf32.f32 %0, %1;" : "=r"(r) : "f"(f));
    return r;
}

// ---------------- scratch ----------------
__device__ __half    g_h1h[(size_t)NN * 128];   // layer1 linear out (fp16, for agg)
__device__ float     g_x2[(size_t)NN * 128];    // layer1 GAT out (relu), gemm2 input
__device__ __half    g_h2h[(size_t)NN * 64];    // layer2 linear out (fp16, for agg)
__device__ float     g_as1[NN * 2];
__device__ float     g_ad1[NN * 2];
__device__ float     g_as2[NN];
__device__ float     g_ad2[NN];
__device__ int       g_deg[NN];
__device__ int       g_rowptr[NN + 1];
__device__ int       g_cursor[NN];
__device__ int       g_csrc[ETOT];
__device__ int       g_bsum[256];
__device__ int       g_is64;
__device__ unsigned  g_wf1[256 * 128];          // W1 fragment-packed tf32
__device__ unsigned  g_wf2[128 * 64];           // W2 fragment-packed tf32

// ---------------- init: edge dtype probe + zero degrees ----------------
__global__ void k_init(const int* __restrict__ ei32) {
    int i = blockIdx.x * 256 + threadIdx.x;
    if (i < NN) g_deg[i] = 0;
    if (blockIdx.x == 0 && threadIdx.x == 0) {
        int all0 = 1;
        #pragma unroll
        for (int j = 0; j < 32; j++)
            if (ei32[2 * j + 1] != 0) all0 = 0;
        g_is64 = all0;           // int64 values < 50000 => odd words zero
        g_rowptr[NN] = ETOT;
    }
}

__device__ __forceinline__ int edge_at(const void* ei, long long idx) {
    if (g_is64) return (int)((const long long*)ei)[idx];
    return ((const int*)ei)[idx];
}

// ---------------- CSR build ----------------
__global__ void k_count(const void* __restrict__ ei) {
    int idx = blockIdx.x * 256 + threadIdx.x;
    if (idx >= ETOT) return;
    int d = (idx < EE) ? edge_at(ei, (long long)EE + idx) : (idx - EE);
    atomicAdd(&g_deg[d], 1);
}

__global__ void k_scanB() {   // chunk sums + exclusive scan of chunk sums
    __shared__ __align__(16) int sm[256];
    int t = threadIdx.x;
    int sum = 0;
    if (t < NBLK) {
        int base = t * 256;
        if (base + 256 <= NN) {
            const int4* p = (const int4*)&g_deg[base];
            #pragma unroll 8
            for (int j = 0; j < 64; j++) {
                int4 v = p[j];
                sum += v.x + v.y + v.z + v.w;
            }
        } else {
            for (int j = base; j < NN; j++) sum += g_deg[j];
        }
    }
    sm[t] = sum; __syncthreads();
    for (int off = 1; off < 256; off <<= 1) {
        int x = (t >= off) ? sm[t - off] : 0;
        __syncthreads();
        sm[t] += x;
        __syncthreads();
    }
    if (t < NBLK) g_bsum[t] = sm[t] - sum;   // exclusive
}

__global__ void k_scanC() {
    __shared__ __align__(16) int sm[256];
    int b = blockIdx.x, t = threadIdx.x;
    int i = b * 256 + t;
    int v = (i < NN) ? g_deg[i] : 0;
    sm[t] = v; __syncthreads();
    for (int off = 1; off < 256; off <<= 1) {
        int x = (t >= off) ? sm[t - off] : 0;
        __syncthreads();
        sm[t] += x;
        __syncthreads();
    }
    if (i < NN) {
        int rp = g_bsum[b] + sm[t] - v;
        g_rowptr[i] = rp;
        g_cursor[i] = rp;
    }
}

__global__ void k_scatter(const void* __restrict__ ei) {
    int idx = blockIdx.x * 256 + threadIdx.x;
    if (idx >= ETOT) return;
    int s, d;
    if (idx < EE) {
        s = edge_at(ei, idx);
        d = edge_at(ei, (long long)EE + idx);
    } else {
        s = d = idx - EE;
    }
    int pos = atomicAdd(&g_cursor[d], 1);
    g_csrc[pos] = s;
}

// ---------------- W fragment pre-pack (runs once, tiny) ----------------
// B-frag mapping (m16n8k8.row.col, verified): for W[k][n]:
//   k8 = k>>3, nt = n>>3, lane = (n&7)*4 + (k&3), reg = (k>>2)&1
template<int K, int NOUT>
__global__ void k_packW(const float* __restrict__ W, unsigned* __restrict__ wf) {
    int i = blockIdx.x * 256 + threadIdx.x;
    if (i >= K * NOUT) return;
    int k = i / NOUT, n = i % NOUT;
    constexpr int NT = NOUT / 8;
    int k8 = k >> 3, nt = n >> 3;
    int lane = (n & 7) * 4 + (k & 3);
    int reg = (k >> 2) & 1;
    wf[(((k8 * NT + nt) * 32) + lane) * 2 + reg] = f2tf32(W[i]);
}

// ---------------- TF32 tensor-core GEMM + fused attention-score epilogue --------
// A staged via register prefetch -> smem (tf32); B fragments from pre-packed
// global (coalesced LDG.64, L1/L2 resident).
template<int K, int NOUT, int H>
__global__ void __launch_bounds__(256, 2) k_gemm_tc(
        const float* __restrict__ X, const unsigned* __restrict__ wf,
        const float* __restrict__ att_s, const float* __restrict__ att_d,
        __half* __restrict__ Hout16, float* __restrict__ as_, float* __restrict__ ad_,
        int n) {
    constexpr int NT = NOUT / 8;    // n-tiles (16 for 128, 8 for 64)
    constexpr int MT = 128;         // rows per block
    constexpr int KT = 32;          // k chunk (4 k8-steps)
    constexpr int XS = KT + 4;      // padded word stride (36)
    constexpr int NC = K / KT;      // chunks

    __shared__ __align__(16) unsigned xs[MT][XS];

    int tid = threadIdx.x;
    int w = tid >> 5, l = tid & 31;
    int tg = l & 3;      // tid in quad
    int gp = l >> 2;     // quad id
    int m0 = blockIdx.x * MT;
    int rowA = w * 16 + gp;

    float acc[NT][4];
#pragma unroll
    for (int nt = 0; nt < NT; nt++)
#pragma unroll
        for (int c = 0; c < 4; c++) acc[nt][c] = 0.f;

    // per-thread staging coords (4 float4 per chunk)
    int sr[4], sc4[4];
#pragma unroll
    for (int j = 0; j < 4; j++) {
        int i = tid + j * 256;
        sr[j] = i >> 3;
        sc4[j] = i & 7;
    }

    float4 pre[4];
    // preload chunk 0
#pragma unroll
    for (int j = 0; j < 4; j++) {
        int gr = m0 + sr[j];
        pre[j] = make_float4(0.f, 0.f, 0.f, 0.f);
        if (gr < n) pre[j] = *(const float4*)&X[(size_t)gr * K + sc4[j] * 4];
    }

#pragma unroll
    for (int kc = 0; kc < NC; kc++) {
        // store staged chunk (convert to tf32 at STS)
#pragma unroll
        for (int j = 0; j < 4; j++) {
            uint4 u;
            u.x = f2tf32(pre[j].x); u.y = f2tf32(pre[j].y);
            u.z = f2tf32(pre[j].z); u.w = f2tf32(pre[j].w);
            *(uint4*)&xs[sr[j]][sc4[j] * 4] = u;
        }
        __syncthreads();
        // prefetch next chunk while computing this one
        if (kc + 1 < NC) {
            int k0n = (kc + 1) * KT;
#pragma unroll
            for (int j = 0; j < 4; j++) {
                int gr = m0 + sr[j];
                pre[j] = make_float4(0.f, 0.f, 0.f, 0.f);
                if (gr < n) pre[j] = *(const float4*)&X[(size_t)gr * K + k0n + sc4[j] * 4];
            }
        }
        int kb = kc * 4;   // global k8 base
#pragma unroll
        for (int k8 = 0; k8 < 4; k8++) {
            unsigned a0 = xs[rowA][k8 * 8 + tg];
            unsigned a1 = xs[rowA + 8][k8 * 8 + tg];
            unsigned a2 = xs[rowA][k8 * 8 + tg + 4];
            unsigned a3 = xs[rowA + 8][k8 * 8 + tg + 4];
            const uint2* wp = (const uint2*)wf + (size_t)(kb + k8) * NT * 32 + l;
#pragma unroll
            for (int nt = 0; nt < NT; nt++) {
                uint2 B = wp[nt * 32];
                asm volatile(
                    "mma.sync.aligned.m16n8k8.row.col.f32.tf32.tf32.f32 "
                    "{%0,%1,%2,%3},{%4,%5,%6,%7},{%8,%9},{%0,%1,%2,%3};"
                    : "+f"(acc[nt][0]), "+f"(acc[nt][1]),
                      "+f"(acc[nt][2]), "+f"(acc[nt][3])
                    : "r"(a0), "r"(a1), "r"(a2), "r"(a3),
                      "r"(B.x), "r"(B.y));
            }
        }
        __syncthreads();
    }

    // ---- epilogue: fp16 h store + attention scores (verified) ----
    // C frag: c0=(gp, tg*2), c1=(gp, tg*2+1), c2=(gp+8, tg*2), c3=(gp+8, tg*2+1)
    int r0 = m0 + w * 16 + gp;
    int r1 = r0 + 8;

    float ps0[H], pd0[H], ps1[H], pd1[H];
#pragma unroll
    for (int h = 0; h < H; h++) { ps0[h] = pd0[h] = ps1[h] = pd1[h] = 0.f; }

#pragma unroll
    for (int nt = 0; nt < NT; nt++) {
        int col = nt * 8 + tg * 2;
        float s0 = att_s[col], s1 = att_s[col + 1];
        float d0 = att_d[col], d1 = att_d[col + 1];
        int h = (H == 2) ? (nt / (NT / 2)) : 0;
        ps0[h] += acc[nt][0] * s0 + acc[nt][1] * s1;
        pd0[h] += acc[nt][0] * d0 + acc[nt][1] * d1;
        ps1[h] += acc[nt][2] * s0 + acc[nt][3] * s1;
        pd1[h] += acc[nt][2] * d0 + acc[nt][3] * d1;
    }
#pragma unroll
    for (int h = 0; h < H; h++) {
#pragma unroll
        for (int o = 1; o < 4; o <<= 1) {
            ps0[h] += __shfl_xor_sync(0xffffffffu, ps0[h], o);
            pd0[h] += __shfl_xor_sync(0xffffffffu, pd0[h], o);
            ps1[h] += __shfl_xor_sync(0xffffffffu, ps1[h], o);
            pd1[h] += __shfl_xor_sync(0xffffffffu, pd1[h], o);
        }
    }

    if (r0 < n) {
#pragma unroll
        for (int nt = 0; nt < NT; nt++) {
            int col = nt * 8 + tg * 2;
            *(unsigned*)&Hout16[(size_t)r0 * NOUT + col] =
                h2_to_u32(__floats2half2_rn(acc[nt][0], acc[nt][1]));
        }
        if (tg == 0) {
#pragma unroll
            for (int h = 0; h < H; h++) {
                as_[r0 * H + h] = ps0[h];
                ad_[r0 * H + h] = pd0[h];
            }
        }
    }
    if (r1 < n) {
#pragma unroll
        for (int nt = 0; nt < NT; nt++) {
            int col = nt * 8 + tg * 2;
            *(unsigned*)&Hout16[(size_t)r1 * NOUT + col] =
                h2_to_u32(__floats2half2_rn(acc[nt][2], acc[nt][3]));
        }
        if (tg == 0) {
#pragma unroll
            for (int h = 0; h < H; h++) {
                as_[r1 * H + h] = ps1[h];
                ad_[r1 * H + h] = pd1[h];
            }
        }
    }
}

// ---------------- single-pass softmax aggregation (warp per dst node) ----------------
template<int NOUT, int H, int VEC, bool RELU, bool LOGSM>
__global__ void k_agg(const __half* __restrict__ Hsrc,
                      const float* __restrict__ as_, const float* __restrict__ ad_,
                      const float* __restrict__ bias, float* __restrict__ out, int n) {
    int node = blockIdx.x * (blockDim.x / 32) + (threadIdx.x >> 5);
    int lane = threadIdx.x & 31;
    if (node >= n) return;

    int head = (lane * VEC) / 64;
    float adv = ad_[node * H + head];
    int beg = g_rowptr[node];
    int end = g_rowptr[node + 1];

    float den = 0.f;
    float acc[VEC];
#pragma unroll
    for (int j = 0; j < VEC; j++) acc[j] = 0.f;

    const __half* Hbase = Hsrc + lane * VEC;

    int i = beg;
    for (; i + 4 <= end; i += 4) {
        int s0 = g_csrc[i],     s1 = g_csrc[i + 1];
        int s2 = g_csrc[i + 2], s3 = g_csrc[i + 3];
        float v0 = as_[s0 * H + head] + adv;
        float v1 = as_[s1 * H + head] + adv;
        float v2 = as_[s2 * H + head] + adv;
        float v3 = as_[s3 * H + head] + adv;
        v0 = v0 > 0.f ? v0 : 0.2f * v0;
        v1 = v1 > 0.f ? v1 : 0.2f * v1;
        v2 = v2 > 0.f ? v2 : 0.2f * v2;
        v3 = v3 > 0.f ? v3 : 0.2f * v3;
        float w0 = __expf(v0), w1 = __expf(v1);
        float w2 = __expf(v2), w3 = __expf(v3);
        den += (w0 + w1) + (w2 + w3);
        if (VEC == 4) {
            uint2 u0 = *(const uint2*)(Hbase + (size_t)s0 * NOUT);
            uint2 u1 = *(const uint2*)(Hbase + (size_t)s1 * NOUT);
            uint2 u2 = *(const uint2*)(Hbase + (size_t)s2 * NOUT);
            uint2 u3 = *(const uint2*)(Hbase + (size_t)s3 * NOUT);
            float2 a0 = u32_to_f2(u0.x), a1 = u32_to_f2(u0.y);
            float2 b0 = u32_to_f2(u1.x), b1 = u32_to_f2(u1.y);
            float2 c0 = u32_to_f2(u2.x), c1 = u32_to_f2(u2.y);
            float2 d0 = u32_to_f2(u3.x), d1 = u32_to_f2(u3.y);
            acc[0] += (w0 * a0.x + w1 * b0.x) + (w2 * c0.x + w3 * d0.x);
            acc[1] += (w0 * a0.y + w1 * b0.y) + (w2 * c0.y + w3 * d0.y);
            acc[2] += (w0 * a1.x + w1 * b1.x) + (w2 * c1.x + w3 * d1.x);
            acc[3] += (w0 * a1.y + w1 * b1.y) + (w2 * c1.y + w3 * d1.y);
        } else {
            unsigned u0 = *(const unsigned*)(Hbase + (size_t)s0 * NOUT);
            unsigned u1 = *(const unsigned*)(Hbase + (size_t)s1 * NOUT);
            unsigned u2 = *(const unsigned*)(Hbase + (size_t)s2 * NOUT);
            unsigned u3 = *(const unsigned*)(Hbase + (size_t)s3 * NOUT);
            float2 a = u32_to_f2(u0), b = u32_to_f2(u1);
            float2 c = u32_to_f2(u2), d = u32_to_f2(u3);
            acc[0] += (w0 * a.x + w1 * b.x) + (w2 * c.x + w3 * d.x);
            acc[1] += (w0 * a.y + w1 * b.y) + (w2 * c.y + w3 * d.y);
        }
    }
    for (; i < end; i++) {
        int s = g_csrc[i];
        float v = as_[s * H + head] + adv;
        v = v > 0.f ? v : 0.2f * v;
        float w = __expf(v);
        den += w;
        if (VEC == 4) {
            uint2 u = *(const uint2*)(Hbase + (size_t)s * NOUT);
            float2 a0 = u32_to_f2(u.x);
            float2 a1 = u32_to_f2(u.y);
            acc[0] += w * a0.x; acc[1] += w * a0.y;
            acc[2] += w * a1.x; acc[3] += w * a1.y;
        } else {
            unsigned u = *(const unsigned*)(Hbase + (size_t)s * NOUT);
            float2 a = u32_to_f2(u);
            acc[0] += w * a.x; acc[1] += w * a.y;
        }
    }

    float inv = 1.f / (den + 1e-16f);
    float o[VEC];
#pragma unroll
    for (int j = 0; j < VEC; j++) {
        o[j] = acc[j] * inv + bias[lane * VEC + j];
        if (RELU) o[j] = fmaxf(o[j], 0.f);
    }

    if (LOGSM) {   // VEC==2, NOUT==64: warp holds all 64 outputs
        float m = fmaxf(o[0], o[1]);
#pragma unroll
        for (int off = 16; off > 0; off >>= 1)
            m = fmaxf(m, __shfl_xor_sync(0xffffffffu, m, off));
        float s_ = __expf(o[0] - m) + __expf(o[1] - m);
#pragma unroll
        for (int off = 16; off > 0; off >>= 1)
            s_ += __shfl_xor_sync(0xffffffffu, s_, off);
        float ls = m + logf(s_);
#pragma unroll
        for (int j = 0; j < VEC; j++) o[j] -= ls;
    }

    float* op = out + (size_t)node * NOUT + lane * VEC;
    if (VEC == 4) *(float4*)op = make_float4(o[0], o[1], o[2], o[3]);
    else          *(float2*)op = make_float2(o[0], o[1]);
}

// ---------------- launch ----------------
extern "C" void kernel_launch(void* const* d_in, const int* in_sizes, int n_in,
                              void* d_out, int out_size) {
    const float* x    = (const float*)d_in[0];
    const void*  ei   = d_in[1];
    const float* W1   = (const float*)d_in[2];
    const float* asw1 = (const float*)d_in[3];
    const float* adw1 = (const float*)d_in[4];
    const float* b1   = (const float*)d_in[5];
    const float* W2   = (const float*)d_in[6];
    const float* asw2 = (const float*)d_in[7];
    const float* adw2 = (const float*)d_in[8];
    const float* b2   = (const float*)d_in[9];
    float*       out  = (float*)d_out;

    const int EB = (ETOT + 255) / 256;
    const int WB = (NN + 7) / 8;
    const int GB = (NN + 127) / 128;    // gemm grid (128 rows/block)

    __half*   h1h = nullptr; cudaGetSymbolAddress((void**)&h1h, g_h1h);
    __half*   h2h = nullptr; cudaGetSymbolAddress((void**)&h2h, g_h2h);
    float*    x2  = nullptr; cudaGetSymbolAddress((void**)&x2,  g_x2);
    float*    as1 = nullptr; cudaGetSymbolAddress((void**)&as1, g_as1);
    float*    ad1 = nullptr; cudaGetSymbolAddress((void**)&ad1, g_ad1);
    float*    as2 = nullptr; cudaGetSymbolAddress((void**)&as2, g_as2);
    float*    ad2 = nullptr; cudaGetSymbolAddress((void**)&ad2, g_ad2);
    unsigned* wf1 = nullptr; cudaGetSymbolAddress((void**)&wf1, g_wf1);
    unsigned* wf2 = nullptr; cudaGetSymbolAddress((void**)&wf2, g_wf2);

    // side stream + events for fork/join (created once, on the first —
    // non-captured — correctness call; reused as graph dependencies later)
    static cudaStream_t s2 = nullptr;
    static cudaEvent_t  e0 = nullptr, e1 = nullptr;
    if (!s2) {
        cudaStreamCreateWithFlags(&s2, cudaStreamNonBlocking);
        cudaEventCreateWithFlags(&e0, cudaEventDisableTiming);
        cudaEventCreateWithFlags(&e1, cudaEventDisableTiming);
    }

    // fork: GEMM chain on s2, CSR chain on the main stream
    cudaEventRecord(e0, 0);
    cudaStreamWaitEvent(s2, e0, 0);

    k_init<<<NBLK, 256>>>((const int*)ei);                                   // 0 (main)
    k_count<<<EB, 256>>>(ei);                                                // 1 (main)
    k_packW<256, 128><<<(256 * 128 + 255) / 256, 256, 0, s2>>>(W1, wf1);     // 2 (s2)
    k_gemm_tc<256, 128, 2><<<GB, 256, 0, s2>>>(                              // 3 (s2, profiled)
        x, wf1, asw1, adw1, h1h, as1, ad1, NN);
    k_packW<128, 64><<<(128 * 64 + 255) / 256, 256, 0, s2>>>(W2, wf2);       // 4 (s2)
    cudaEventRecord(e1, s2);

    k_scanB<<<1, 256>>>();                                                   // 5 (main)
    k_scanC<<<NBLK, 256>>>();                                                // 6 (main)
    k_scatter<<<EB, 256>>>(ei);                                              // 7 (main)

    // join: aggregation needs CSR (main) + h1/scores/wf2 (s2)
    cudaStreamWaitEvent(0, e1, 0);

    k_agg<128, 2, 4, true, false><<<WB, 256>>>(h1h, as1, ad1, b1, x2, NN);   // 8
    k_gemm_tc<128, 64, 1><<<GB, 256>>>(                                      // 9
        x2, wf2, asw2, adw2, h2h, as2, ad2, NN);
    k_agg<64, 1, 2, false, true><<<WB, 256>>>(h2h, as2, ad2, b2, out, NN);   // 10
}

// round 10
// speedup vs baseline: 1.5389x; 1.0850x over previous
#include <cuda_runtime.h>
#include <cuda_fp16.h>
#include <math.h>

#define NN 50000
#define EE 1600000
#define ETOT (EE + NN)          // edges + self loops
#define NBLK 196                // ceil(NN/256)

// ---------------- bit casts / conversions ----------------
__device__ __forceinline__ unsigned h2_to_u32(__half2 h) {
    return *reinterpret_cast<unsigned*>(&h);
}
__device__ __forceinline__ float2 u32_to_f2(unsigned u) {
    __half2 h = *reinterpret_cast<__half2*>(&u);
    return __half22float2(h);
}
__device__ __forceinline__ unsigned f2tf32(float f) {
    unsigned r;
    asm("cvt.rna.tf32.f32 %0, %1;" : "=r"(r) : "f"(f));
    return r;
}

// ---------------- scratch ----------------
__device__ __half    g_h1h[(size_t)NN * 128];   // layer1 linear out (fp16, for agg)
__device__ float     g_x2[(size_t)NN * 128];    // layer1 GAT out (relu), gemm2 input
__device__ __half    g_h2h[(size_t)NN * 64];    // layer2 linear out (fp16, for agg)
__device__ float     g_as1[NN * 2];
__device__ float     g_ad1[NN * 2];
__device__ float     g_as2[NN];
__device__ float     g_ad2[NN];
__device__ int       g_deg[NN];
__device__ int       g_rowptr[NN + 1];
__device__ int       g_cursor[NN];
__device__ int       g_csrc[ETOT];
__device__ int       g_bsum[256];
__device__ int       g_is64;
__device__ unsigned  g_wf1[256 * 128];          // W1 fragment-packed tf32
__device__ unsigned  g_wf2[128 * 64];           // W2 fragment-packed tf32

// ---------------- init: edge dtype probe + zero degrees ----------------
__global__ void k_init(const int* __restrict__ ei32) {
    int i = blockIdx.x * 256 + threadIdx.x;
    if (i < NN) g_deg[i] = 0;
    if (blockIdx.x == 0 && threadIdx.x == 0) {
        int all0 = 1;
        #pragma unroll
        for (int j = 0; j < 32; j++)
            if (ei32[2 * j + 1] != 0) all0 = 0;
        g_is64 = all0;           // int64 values < 50000 => odd words zero
        g_rowptr[NN] = ETOT;
    }
}

__device__ __forceinline__ int edge_at(const void* ei, long long idx) {
    if (g_is64) return (int)((const long long*)ei)[idx];
    return ((const int*)ei)[idx];
}

// ---------------- CSR build ----------------
__global__ void k_count(const void* __restrict__ ei) {
    int idx = blockIdx.x * 256 + threadIdx.x;
    if (idx >= ETOT) return;
    int d = (idx < EE) ? edge_at(ei, (long long)EE + idx) : (idx - EE);
    atomicAdd(&g_deg[d], 1);
}

__global__ void k_scanB() {   // chunk sums + exclusive scan of chunk sums
    __shared__ __align__(16) int sm[256];
    int t = threadIdx.x;
    int sum = 0;
    if (t < NBLK) {
        int base = t * 256;
        if (base + 256 <= NN) {
            const int4* p = (const int4*)&g_deg[base];
            #pragma unroll 8
            for (int j = 0; j < 64; j++) {
                int4 v = p[j];
                sum += v.x + v.y + v.z + v.w;
            }
        } else {
            for (int j = base; j < NN; j++) sum += g_deg[j];
        }
    }
    sm[t] = sum; __syncthreads();
    for (int off = 1; off < 256; off <<= 1) {
        int x = (t >= off) ? sm[t - off] : 0;
        __syncthreads();
        sm[t] += x;
        __syncthreads();
    }
    if (t < NBLK) g_bsum[t] = sm[t] - sum;   // exclusive
}

__global__ void k_scanC() {
    __shared__ __align__(16) int sm[256];
    int b = blockIdx.x, t = threadIdx.x;
    int i = b * 256 + t;
    int v = (i < NN) ? g_deg[i] : 0;
    sm[t] = v; __syncthreads();
    for (int off = 1; off < 256; off <<= 1) {
        int x = (t >= off) ? sm[t - off] : 0;
        __syncthreads();
        sm[t] += x;
        __syncthreads();
    }
    if (i < NN) {
        int rp = g_bsum[b] + sm[t] - v;
        g_rowptr[i] = rp;
        g_cursor[i] = rp;
    }
}

__global__ void k_scatter(const void* __restrict__ ei) {
    int idx = blockIdx.x * 256 + threadIdx.x;
    if (idx >= ETOT) return;
    int s, d;
    if (idx < EE) {
        s = edge_at(ei, idx);
        d = edge_at(ei, (long long)EE + idx);
    } else {
        s = d = idx - EE;
    }
    int pos = atomicAdd(&g_cursor[d], 1);
    g_csrc[pos] = s;
}

// ---------------- W fragment pre-pack ----------------
// B-frag mapping (m16n8k8.row.col, verified): for W[k][n]:
//   k8 = k>>3, nt = n>>3, lane = (n&7)*4 + (k&3), reg = (k>>2)&1
template<int K, int NOUT>
__global__ void k_packW(const float* __restrict__ W, unsigned* __restrict__ wf) {
    int i = blockIdx.x * 256 + threadIdx.x;
    if (i >= K * NOUT) return;
    int k = i / NOUT, n = i % NOUT;
    constexpr int NT = NOUT / 8;
    int k8 = k >> 3, nt = n >> 3;
    int lane = (n & 7) * 4 + (k & 3);
    int reg = (k >> 2) & 1;
    wf[(((k8 * NT + nt) * 32) + lane) * 2 + reg] = f2tf32(W[i]);
}

// ---------------- TF32 tensor-core GEMM + fused attention-score epilogue --------
// MT=64 rows, warps split 4(M) x 2(N-halves). A via register prefetch -> smem;
// B fragments from pre-packed global (coalesced LDG.64, L2 resident).
template<int K, int NOUT, int H>
__global__ void __launch_bounds__(256, 3) k_gemm_tc(
        const float* __restrict__ X, const unsigned* __restrict__ wf,
        const float* __restrict__ att_s, const float* __restrict__ att_d,
        __half* __restrict__ Hout16, float* __restrict__ as_, float* __restrict__ ad_,
        int n) {
    constexpr int NT  = NOUT / 8;
    constexpr int NT2 = NT / 2;     // n-tiles per warp
    constexpr int MT  = 64;         // rows per block
    constexpr int KT  = 32;         // k chunk (4 k8-steps)
    constexpr int XS  = KT + 4;
    constexpr int NC  = K / KT;

    __shared__ __align__(16) unsigned xs[MT][XS];

    int tid = threadIdx.x;
    int w = tid >> 5, l = tid & 31;
    int tg = l & 3, gp = l >> 2;
    int wm = w & 3, wn = w >> 2;   // M group, N half
    int m0 = blockIdx.x * MT;
    int rowA = wm * 16 + gp;

    float acc[NT2][4];
#pragma unroll
    for (int nt = 0; nt < NT2; nt++)
#pragma unroll
        for (int c = 0; c < 4; c++) acc[nt][c] = 0.f;

    // staging coords: 64*8=512 float4, 2 per thread
    int sr[2], sc4[2];
#pragma unroll
    for (int j = 0; j < 2; j++) {
        int i = tid + j * 256;
        sr[j] = i >> 3;
        sc4[j] = i & 7;
    }
    float4 pre[2];
#pragma unroll
    for (int j = 0; j < 2; j++) {
        int gr = m0 + sr[j];
        pre[j] = make_float4(0.f, 0.f, 0.f, 0.f);
        if (gr < n) pre[j] = *(const float4*)&X[(size_t)gr * K + sc4[j] * 4];
    }

#pragma unroll
    for (int kc = 0; kc < NC; kc++) {
#pragma unroll
        for (int j = 0; j < 2; j++) {
            uint4 u;
            u.x = f2tf32(pre[j].x); u.y = f2tf32(pre[j].y);
            u.z = f2tf32(pre[j].z); u.w = f2tf32(pre[j].w);
            *(uint4*)&xs[sr[j]][sc4[j] * 4] = u;
        }
        __syncthreads();
        if (kc + 1 < NC) {
            int k0n = (kc + 1) * KT;
#pragma unroll
            for (int j = 0; j < 2; j++) {
                int gr = m0 + sr[j];
                pre[j] = make_float4(0.f, 0.f, 0.f, 0.f);
                if (gr < n) pre[j] = *(const float4*)&X[(size_t)gr * K + k0n + sc4[j] * 4];
            }
        }
        int kb = kc * 4;
#pragma unroll
        for (int k8 = 0; k8 < 4; k8++) {
            unsigned a0 = xs[rowA][k8 * 8 + tg];
            unsigned a1 = xs[rowA + 8][k8 * 8 + tg];
            unsigned a2 = xs[rowA][k8 * 8 + tg + 4];
            unsigned a3 = xs[rowA + 8][k8 * 8 + tg + 4];
            const uint2* wp = (const uint2*)wf
                            + (size_t)(kb + k8) * NT * 32 + wn * NT2 * 32 + l;
#pragma unroll
            for (int nt = 0; nt < NT2; nt++) {
                uint2 B = wp[nt * 32];
                asm volatile(
                    "mma.sync.aligned.m16n8k8.row.col.f32.tf32.tf32.f32 "
                    "{%0,%1,%2,%3},{%4,%5,%6,%7},{%8,%9},{%0,%1,%2,%3};"
                    : "+f"(acc[nt][0]), "+f"(acc[nt][1]),
                      "+f"(acc[nt][2]), "+f"(acc[nt][3])
                    : "r"(a0), "r"(a1), "r"(a2), "r"(a3),
                      "r"(B.x), "r"(B.y));
            }
        }
        __syncthreads();
    }

    // ---- epilogue ----
    // C frag rows: r0=(rowA), r1=(rowA+8); cols (wn*NT2+nt)*8 + tg*2 (+1)
    int r0 = m0 + rowA;
    int r1 = r0 + 8;

    float ps0 = 0.f, pd0 = 0.f, ps1 = 0.f, pd1 = 0.f;
#pragma unroll
    for (int nt = 0; nt < NT2; nt++) {
        int col = (wn * NT2 + nt) * 8 + tg * 2;
        float s0 = att_s[col], s1 = att_s[col + 1];
        float d0 = att_d[col], d1 = att_d[col + 1];
        ps0 += acc[nt][0] * s0 + acc[nt][1] * s1;
        pd0 += acc[nt][0] * d0 + acc[nt][1] * d1;
        ps1 += acc[nt][2] * s0 + acc[nt][3] * s1;
        pd1 += acc[nt][2] * d0 + acc[nt][3] * d1;
    }
#pragma unroll
    for (int o = 1; o < 4; o <<= 1) {
        ps0 += __shfl_xor_sync(0xffffffffu, ps0, o);
        pd0 += __shfl_xor_sync(0xffffffffu, pd0, o);
        ps1 += __shfl_xor_sync(0xffffffffu, ps1, o);
        pd1 += __shfl_xor_sync(0xffffffffu, pd1, o);
    }

    // h stores (each warp stores its N-half)
    if (r0 < n) {
#pragma unroll
        for (int nt = 0; nt < NT2; nt++) {
            int col = (wn * NT2 + nt) * 8 + tg * 2;
            *(unsigned*)&Hout16[(size_t)r0 * NOUT + col] =
                h2_to_u32(__floats2half2_rn(acc[nt][0], acc[nt][1]));
        }
    }
    if (r1 < n) {
#pragma unroll
        for (int nt = 0; nt < NT2; nt++) {
            int col = (wn * NT2 + nt) * 8 + tg * 2;
            *(unsigned*)&Hout16[(size_t)r1 * NOUT + col] =
                h2_to_u32(__floats2half2_rn(acc[nt][2], acc[nt][3]));
        }
    }

    if (H == 2) {
        // each N-half is exactly one head
        if (tg == 0) {
            if (r0 < n) { as_[r0 * 2 + wn] = ps0; ad_[r0 * 2 + wn] = pd0; }
            if (r1 < n) { as_[r1 * 2 + wn] = ps1; ad_[r1 * 2 + wn] = pd1; }
        }
    } else {
        // combine the two N-half partials via smem (deterministic)
        float* sb = (float*)xs;   // mainloop done (post-sync), safe to reuse
        if (wn == 1 && tg == 0) {
            sb[wm * 32 + gp * 2 + 0]       = ps0;
            sb[wm * 32 + gp * 2 + 1]       = pd0;
            sb[wm * 32 + (gp + 8) * 2 + 0] = ps1;
            sb[wm * 32 + (gp + 8) * 2 + 1] = pd1;
        }
        __syncthreads();
        if (wn == 0 && tg == 0) {
            ps0 += sb[wm * 32 + gp * 2 + 0];
            pd0 += sb[wm * 32 + gp * 2 + 1];
            ps1 += sb[wm * 32 + (gp + 8) * 2 + 0];
            pd1 += sb[wm * 32 + (gp + 8) * 2 + 1];
            if (r0 < n) { as_[r0] = ps0; ad_[r0] = pd0; }
            if (r1 < n) { as_[r1] = ps1; ad_[r1] = pd1; }
        }
    }
}

// ---------------- single-pass softmax aggregation (warp per dst node) ----------
// Batched edge weights: warp loads a block of csrc coalesced, computes
// leaky+exp for all of them at once, then the inner loop is shuffle + gather.
template<int NOUT, int H, int VEC, bool RELU, bool LOGSM>
__global__ void k_agg(const __half* __restrict__ Hsrc,
                      const float* __restrict__ as_, const float* __restrict__ ad_,
                      const float* __restrict__ bias, float* __restrict__ out, int n) {
    int node = blockIdx.x * (blockDim.x / 32) + (threadIdx.x >> 5);
    int lane = threadIdx.x & 31;
    if (node >= n) return;

    int head = (lane * VEC) / 64;
    float adv0 = ad_[node * H];
    float adv1 = (H == 2) ? ad_[node * H + 1] : adv0;
    int beg = g_rowptr[node];
    int end = g_rowptr[node + 1];

    constexpr int EBK = (H == 2) ? 16 : 32;   // edges per batch

    float den = 0.f;
    float acc[VEC];
#pragma unroll
    for (int j = 0; j < VEC; j++) acc[j] = 0.f;

    const __half* Hbase = Hsrc + lane * VEC;

    for (int base = beg; base < end; base += EBK) {
        // batch load csrc + compute weights (coalesced, one exp per lane)
        int myE = (H == 2) ? (base + (lane >> 1)) : (base + lane);
        int myH = (H == 2) ? (lane & 1) : 0;
        int sj = 0; float wv = 0.f;
        if (myE < end) {
            sj = g_csrc[myE];
            float v = as_[sj * H + myH] + (myH ? adv1 : adv0);
            v = v > 0.f ? v : 0.2f * v;
            wv = __expf(v);
        }
        int cnt = min(EBK, end - base);
        int e = 0;
        for (; e + 4 <= cnt; e += 4) {
            int s0, s1, s2, s3;
            float w0, w1, w2, w3;
            if (H == 2) {
                s0 = __shfl_sync(0xffffffffu, sj, 2 * (e + 0));
                s1 = __shfl_sync(0xffffffffu, sj, 2 * (e + 1));
                s2 = __shfl_sync(0xffffffffu, sj, 2 * (e + 2));
                s3 = __shfl_sync(0xffffffffu, sj, 2 * (e + 3));
                w0 = __shfl_sync(0xffffffffu, wv, 2 * (e + 0) + head);
                w1 = __shfl_sync(0xffffffffu, wv, 2 * (e + 1) + head);
                w2 = __shfl_sync(0xffffffffu, wv, 2 * (e + 2) + head);
                w3 = __shfl_sync(0xffffffffu, wv, 2 * (e + 3) + head);
            } else {
                s0 = __shfl_sync(0xffffffffu, sj, e + 0);
                s1 = __shfl_sync(0xffffffffu, sj, e + 1);
                s2 = __shfl_sync(0xffffffffu, sj, e + 2);
                s3 = __shfl_sync(0xffffffffu, sj, e + 3);
                w0 = __shfl_sync(0xffffffffu, wv, e + 0);
                w1 = __shfl_sync(0xffffffffu, wv, e + 1);
                w2 = __shfl_sync(0xffffffffu, wv, e + 2);
                w3 = __shfl_sync(0xffffffffu, wv, e + 3);
            }
            den += (w0 + w1) + (w2 + w3);
            if (VEC == 4) {
                uint2 u0 = *(const uint2*)(Hbase + (size_t)s0 * NOUT);
                uint2 u1 = *(const uint2*)(Hbase + (size_t)s1 * NOUT);
                uint2 u2 = *(const uint2*)(Hbase + (size_t)s2 * NOUT);
                uint2 u3 = *(const uint2*)(Hbase + (size_t)s3 * NOUT);
                float2 a0 = u32_to_f2(u0.x), a1 = u32_to_f2(u0.y);
                float2 b0 = u32_to_f2(u1.x), b1 = u32_to_f2(u1.y);
                float2 c0 = u32_to_f2(u2.x), c1 = u32_to_f2(u2.y);
                float2 d0 = u32_to_f2(u3.x), d1 = u32_to_f2(u3.y);
                acc[0] += (w0 * a0.x + w1 * b0.x) + (w2 * c0.x + w3 * d0.x);
                acc[1] += (w0 * a0.y + w1 * b0.y) + (w2 * c0.y + w3 * d0.y);
                acc[2] += (w0 * a1.x + w1 * b1.x) + (w2 * c1.x + w3 * d1.x);
                acc[3] += (w0 * a1.y + w1 * b1.y) + (w2 * c1.y + w3 * d1.y);
            } else {
                unsigned u0 = *(const unsigned*)(Hbase + (size_t)s0 * NOUT);
                unsigned u1 = *(const unsigned*)(Hbase + (size_t)s1 * NOUT);
                unsigned u2 = *(const unsigned*)(Hbase + (size_t)s2 * NOUT);
                unsigned u3 = *(const unsigned*)(Hbase + (size_t)s3 * NOUT);
                float2 a = u32_to_f2(u0), b = u32_to_f2(u1);
                float2 c = u32_to_f2(u2), d = u32_to_f2(u3);
                acc[0] += (w0 * a.x + w1 * b.x) + (w2 * c.x + w3 * d.x);
                acc[1] += (w0 * a.y + w1 * b.y) + (w2 * c.y + w3 * d.y);
            }
        }
        for (; e < cnt; e++) {
            int s  = __shfl_sync(0xffffffffu, sj, (H == 2) ? 2 * e : e);
            float ww = __shfl_sync(0xffffffffu, wv, (H == 2) ? 2 * e + head : e);
            den += ww;
            if (VEC == 4) {
                uint2 u = *(const uint2*)(Hbase + (size_t)s * NOUT);
                float2 a0 = u32_to_f2(u.x);
                float2 a1 = u32_to_f2(u.y);
                acc[0] += ww * a0.x; acc[1] += ww * a0.y;
                acc[2] += ww * a1.x; acc[3] += ww * a1.y;
            } else {
                unsigned u = *(const unsigned*)(Hbase + (size_t)s * NOUT);
                float2 a = u32_to_f2(u);
                acc[0] += ww * a.x; acc[1] += ww * a.y;
            }
        }
    }

    float inv = 1.f / (den + 1e-16f);
    float o[VEC];
#pragma unroll
    for (int j = 0; j < VEC; j++) {
        o[j] = acc[j] * inv + bias[lane * VEC + j];
        if (RELU) o[j] = fmaxf(o[j], 0.f);
    }

    if (LOGSM) {   // VEC==2, NOUT==64: warp holds all 64 outputs
        float m = fmaxf(o[0], o[1]);
#pragma unroll
        for (int off = 16; off > 0; off >>= 1)
            m = fmaxf(m, __shfl_xor_sync(0xffffffffu, m, off));
        float s_ = __expf(o[0] - m) + __expf(o[1] - m);
#pragma unroll
        for (int off = 16; off > 0; off >>= 1)
            s_ += __shfl_xor_sync(0xffffffffu, s_, off);
        float ls = m + logf(s_);
#pragma unroll
        for (int j = 0; j < VEC; j++) o[j] -= ls;
    }

    float* op = out + (size_t)node * NOUT + lane * VEC;
    if (VEC == 4) *(float4*)op = make_float4(o[0], o[1], o[2], o[3]);
    else          *(float2*)op = make_float2(o[0], o[1]);
}

// ---------------- launch ----------------
extern "C" void kernel_launch(void* const* d_in, const int* in_sizes, int n_in,
                              void* d_out, int out_size) {
    const float* x    = (const float*)d_in[0];
    const void*  ei   = d_in[1];
    const float* W1   = (const float*)d_in[2];
    const float* asw1 = (const float*)d_in[3];
    const float* adw1 = (const float*)d_in[4];
    const float* b1   = (const float*)d_in[5];
    const float* W2   = (const float*)d_in[6];
    const float* asw2 = (const float*)d_in[7];
    const float* adw2 = (const float*)d_in[8];
    const float* b2   = (const float*)d_in[9];
    float*       out  = (float*)d_out;

    const int EB = (ETOT + 255) / 256;
    const int WB = (NN + 7) / 8;
    const int GB = (NN + 63) / 64;      // gemm grid (64 rows/block)

    __half*   h1h = nullptr; cudaGetSymbolAddress((void**)&h1h, g_h1h);
    __half*   h2h = nullptr; cudaGetSymbolAddress((void**)&h2h, g_h2h);
    float*    x2  = nullptr; cudaGetSymbolAddress((void**)&x2,  g_x2);
    float*    as1 = nullptr; cudaGetSymbolAddress((void**)&as1, g_as1);
    float*    ad1 = nullptr; cudaGetSymbolAddress((void**)&ad1, g_ad1);
    float*    as2 = nullptr; cudaGetSymbolAddress((void**)&as2, g_as2);
    float*    ad2 = nullptr; cudaGetSymbolAddress((void**)&ad2, g_ad2);
    unsigned* wf1 = nullptr; cudaGetSymbolAddress((void**)&wf1, g_wf1);
    unsigned* wf2 = nullptr; cudaGetSymbolAddress((void**)&wf2, g_wf2);

    // side stream + events for fork/join (created on first, non-captured call)
    static cudaStream_t s2 = nullptr;
    static cudaEvent_t  e0 = nullptr, e1 = nullptr;
    if (!s2) {
        cudaStreamCreateWithFlags(&s2, cudaStreamNonBlocking);
        cudaEventCreateWithFlags(&e0, cudaEventDisableTiming);
        cudaEventCreateWithFlags(&e1, cudaEventDisableTiming);
    }

    // fork: GEMM chain on s2, CSR chain on the main stream
    cudaEventRecord(e0, 0);
    cudaStreamWaitEvent(s2, e0, 0);

    k_init<<<NBLK, 256>>>((const int*)ei);                                   // main
    k_count<<<EB, 256>>>(ei);                                                // main
    k_packW<256, 128><<<(256 * 128 + 255) / 256, 256, 0, s2>>>(W1, wf1);     // s2
    k_gemm_tc<256, 128, 2><<<GB, 256, 0, s2>>>(                              // s2
        x, wf1, asw1, adw1, h1h, as1, ad1, NN);
    k_packW<128, 64><<<(128 * 64 + 255) / 256, 256, 0, s2>>>(W2, wf2);       // s2
    cudaEventRecord(e1, s2);

    k_scanB<<<1, 256>>>();                                                   // main
    k_scanC<<<NBLK, 256>>>();                                                // main
    k_scatter<<<EB, 256>>>(ei);                                              // main

    // join: aggregation needs CSR (main) + h1/scores/wf2 (s2)
    cudaStreamWaitEvent(0, e1, 0);

    k_agg<128, 2, 4, true, false><<<WB, 256>>>(h1h, as1, ad1, b1, x2, NN);
    k_gemm_tc<128, 64, 1><<<GB, 256>>>(
        x2, wf2, asw2, adw2, h2h, as2, ad2, NN);
    k_agg<64, 1, 2, false, true><<<WB, 256>>>(h2h, as2, ad2, b2, out, NN);
}